// round 1
// baseline (speedup 1.0000x reference)
#include <cuda_runtime.h>
#include <cuda_bf16.h>

// Problem constants
#define Bb 8
#define NSEQ 1024
#define DIM 768
#define HEADS 12
#define HD 64
#define TOPK 100
#define SCALE_F 0.125f   // 64^-0.5

#define MROWS (Bb*NSEQ)          // 8192
#define QKV_N (3*DIM)            // 2304

// Scratch (static device globals; no runtime allocation allowed)
__device__ float g_q[Bb*HEADS*NSEQ*HD];     // [B,H,N,D], pre-scaled by SCALE
__device__ float g_k[Bb*HEADS*NSEQ*HD];
__device__ float g_v[Bb*HEADS*NSEQ*HD];
__device__ float g_attn[Bb*NSEQ*DIM];       // [B,N,C] attention output

// ---------------------------------------------------------------------------
// SGEMM: C[M,N] = A[M,K] @ B[K,N]
// mode 0: scatter into g_q/g_k/g_v (QKV), q scaled
// mode 1: C = A@B + bias  (A==nullptr means A = g_attn)
// ---------------------------------------------------------------------------
#define BM 128
#define BN 64
#define BK 16
#define TM 8
#define TN 4

__global__ __launch_bounds__(256)
void sgemm_kernel(const float* __restrict__ A, const float* __restrict__ B,
                  float* __restrict__ C, const float* __restrict__ bias,
                  int M, int N, int K, int mode)
{
    if (A == nullptr) A = g_attn;

    __shared__ float As[BK][BM + 4];   // stride 132 -> conflict-free transposed stores
    __shared__ float Bs[BK][BN];

    const int bm = blockIdx.y * BM;
    const int bn = blockIdx.x * BN;
    const int tid = threadIdx.x;
    const int tx = tid & 15;          // 0..15 (N dir)
    const int ty = tid >> 4;          // 0..15 (M dir)

    float acc[TM][TN];
#pragma unroll
    for (int i = 0; i < TM; i++)
#pragma unroll
        for (int j = 0; j < TN; j++) acc[i][j] = 0.f;

    for (int k0 = 0; k0 < K; k0 += BK) {
        // Load A tile (128x16) as float4, store transposed As[k][m]
#pragma unroll
        for (int t = 0; t < 2; t++) {
            int id  = tid + t * 256;         // 0..511
            int row = id >> 2;               // 0..127
            int c4  = id & 3;                // 0..3
            float4 a4 = *(const float4*)(A + (size_t)(bm + row) * K + k0 + c4 * 4);
            As[c4*4+0][row] = a4.x;
            As[c4*4+1][row] = a4.y;
            As[c4*4+2][row] = a4.z;
            As[c4*4+3][row] = a4.w;
        }
        // Load B tile (16x64) as float4
        {
            int row = tid >> 4;              // 0..15
            int c4  = tid & 15;              // 0..15
            float4 b4 = *(const float4*)(B + (size_t)(k0 + row) * N + bn + c4 * 4);
            *(float4*)&Bs[row][c4 * 4] = b4;
        }
        __syncthreads();

#pragma unroll
        for (int kk = 0; kk < BK; kk++) {
            float a[TM], b[TN];
            float4 a40 = *(const float4*)&As[kk][ty * TM + 0];
            float4 a41 = *(const float4*)&As[kk][ty * TM + 4];
            a[0]=a40.x; a[1]=a40.y; a[2]=a40.z; a[3]=a40.w;
            a[4]=a41.x; a[5]=a41.y; a[6]=a41.z; a[7]=a41.w;
            float4 b4 = *(const float4*)&Bs[kk][tx * TN];
            b[0]=b4.x; b[1]=b4.y; b[2]=b4.z; b[3]=b4.w;
#pragma unroll
            for (int i = 0; i < TM; i++)
#pragma unroll
                for (int j = 0; j < TN; j++)
                    acc[i][j] += a[i] * b[j];
        }
        __syncthreads();
    }

    if (mode == 0) {
        // QKV scatter. Column -> (t, h, d); whole BN=64 block is a single (t,h).
#pragma unroll
        for (int i = 0; i < TM; i++) {
            int m  = bm + ty * TM + i;
            int b_ = m >> 10;
            int n_ = m & 1023;
#pragma unroll
            for (int j = 0; j < TN; j++) {
                int col = bn + tx * TN + j;
                int t = col / DIM;
                int r = col - t * DIM;
                int h = r >> 6;
                int d = r & 63;
                float vv = acc[i][j];
                float* dst;
                if (t == 0)      { dst = g_q; vv *= SCALE_F; }
                else if (t == 1)   dst = g_k;
                else               dst = g_v;
                dst[((size_t)((b_ * HEADS + h) << 10) + n_) * HD + d] = vv;
            }
        }
    } else {
#pragma unroll
        for (int i = 0; i < TM; i++) {
            int m = bm + ty * TM + i;
#pragma unroll
            for (int j = 0; j < TN; j++) {
                int col = bn + tx * TN + j;
                C[(size_t)m * N + col] = acc[i][j] + bias[col];
            }
        }
    }
}

// ---------------------------------------------------------------------------
// Fused attention: per (b, h, 16-row tile):
//   S = q_tile @ K^T (warp-per-row, 32 scores/lane in regs)
//   exact top-100 threshold via binary search over monotone float order
//   masked softmax in regs -> P in smem
//   PV: split-j across warps, each lane accumulates all 16 rows (float4 acc[16])
// ---------------------------------------------------------------------------
#define AROWS 16
#define CHUNK 128
#define KVS 17                      // float4 stride (68 floats) -> conflict-free

// smem: q (16*64) + kv (128*68) + p (16*1024)
#define SMEM_FLOATS (AROWS*HD + CHUNK*68 + AROWS*NSEQ)
#define SMEM_BYTES  (SMEM_FLOATS * 4)

__device__ __forceinline__ float ord2f(unsigned k) {
    // inverse of monotone float->uint key
    unsigned u = (k & 0x80000000u) ? (k & 0x7FFFFFFFu) : ~k;
    return __uint_as_float(u);
}

__global__ __launch_bounds__(512)
void attn_kernel()
{
    extern __shared__ float sm[];
    float*  sq   = sm;                       // 1024 floats
    float*  skv  = sq + AROWS * HD;          // 128*68 floats
    float*  sp   = skv + CHUNK * 68;         // 16*1024 floats
    float4* skv4 = (float4*)skv;
    float4* sp4  = (float4*)sp;

    const int tid  = threadIdx.x;
    const int lane = tid & 31;
    const int w    = tid >> 5;               // warp 0..15
    const int n0   = blockIdx.x * AROWS;
    const int h    = blockIdx.y;
    const int b    = blockIdx.z;
    const size_t base = (size_t)(b * HEADS + h) * NSEQ * HD;

    // load q tile (16 x 64)
    {
        const float4* gq4 = (const float4*)(g_q + base + (size_t)n0 * HD);
        float4* sq4 = (float4*)sq;
        for (int i = tid; i < AROWS * HD / 4; i += 512) sq4[i] = gq4[i];
    }

    // ---- S = q @ K^T ----
    float s[32];
    const float4* gk4 = (const float4*)(g_k + base);

#pragma unroll
    for (int c = 0; c < 8; c++) {
        __syncthreads();
        for (int i = tid; i < CHUNK * 16; i += 512) {
            int row = i >> 4, d4 = i & 15;
            skv4[row * KVS + d4] = gk4[(size_t)(c * CHUNK + row) * 16 + d4];
        }
        __syncthreads();

        const float4* qrow = (const float4*)(sq + w * HD);
        float a0 = 0.f, a1 = 0.f, a2 = 0.f, a3 = 0.f;
#pragma unroll
        for (int d4 = 0; d4 < 16; d4++) {
            float4 q4 = qrow[d4];
            float4 k0v = skv4[(0 * 32 + lane) * KVS + d4];
            float4 k1v = skv4[(1 * 32 + lane) * KVS + d4];
            float4 k2v = skv4[(2 * 32 + lane) * KVS + d4];
            float4 k3v = skv4[(3 * 32 + lane) * KVS + d4];
            a0 += q4.x*k0v.x + q4.y*k0v.y + q4.z*k0v.z + q4.w*k0v.w;
            a1 += q4.x*k1v.x + q4.y*k1v.y + q4.z*k1v.z + q4.w*k1v.w;
            a2 += q4.x*k2v.x + q4.y*k2v.y + q4.z*k2v.z + q4.w*k2v.w;
            a3 += q4.x*k3v.x + q4.y*k3v.y + q4.z*k3v.z + q4.w*k3v.w;
        }
        s[c*4+0] = a0; s[c*4+1] = a1; s[c*4+2] = a2; s[c*4+3] = a3;
    }

    // ---- exact top-100 threshold: binary search in monotone key space ----
    unsigned lo = 0x007FFFFFu;     // key(-Inf)
    unsigned hi = 0xFF800000u;     // key(+Inf)
    while (lo < hi) {
        unsigned mid = lo + ((hi - lo + 1u) >> 1);
        float t = ord2f(mid);
        int cnt = 0;
#pragma unroll
        for (int i = 0; i < 32; i++) cnt += (s[i] >= t) ? 1 : 0;
#pragma unroll
        for (int o = 16; o > 0; o >>= 1)
            cnt += __shfl_xor_sync(0xffffffffu, cnt, o);
        if (cnt >= TOPK) lo = mid; else hi = mid - 1u;
    }
    const float kth = ord2f(lo);

    // ---- masked softmax ----
    float m = s[0];
#pragma unroll
    for (int i = 1; i < 32; i++) m = fmaxf(m, s[i]);
#pragma unroll
    for (int o = 16; o > 0; o >>= 1)
        m = fmaxf(m, __shfl_xor_sync(0xffffffffu, m, o));

    float sum = 0.f;
#pragma unroll
    for (int i = 0; i < 32; i++) {
        float p = (s[i] >= kth) ? __expf(s[i] - m) : 0.f;
        s[i] = p;
        sum += p;
    }
#pragma unroll
    for (int o = 16; o > 0; o >>= 1)
        sum += __shfl_xor_sync(0xffffffffu, sum, o);
    const float inv = 1.f / sum;

#pragma unroll
    for (int c = 0; c < 8; c++)
#pragma unroll
        for (int u = 0; u < 4; u++)
            sp[w * NSEQ + c * 128 + u * 32 + lane] = s[c*4+u] * inv;
    // sp writes are consumed after the sync at the top of the PV loop below

    // ---- PV: warp w owns j-offsets [w*8, w*8+8) of every 128-chunk ----
    float4 acc[AROWS];
#pragma unroll
    for (int r = 0; r < AROWS; r++) acc[r] = make_float4(0.f, 0.f, 0.f, 0.f);

    const int d4 = lane & 15;
    const int js = lane >> 4;     // 0 or 1
    const float4* gv4 = (const float4*)(g_v + base);

#pragma unroll
    for (int c = 0; c < 8; c++) {
        __syncthreads();          // protects skv reuse AND (c==0) sp visibility
        for (int i = tid; i < CHUNK * 16; i += 512) {
            int row = i >> 4, dd = i & 15;
            skv4[row * KVS + dd] = gv4[(size_t)(c * CHUNK + row) * 16 + dd];
        }
        __syncthreads();

#pragma unroll
        for (int jj = 0; jj < 8; jj += 2) {
            int jl = w * 8 + jj + js;          // local j in chunk
            int jg = c * 128 + jl;             // global j
            float4 v4 = skv4[jl * KVS + d4];
#pragma unroll
            for (int r = 0; r < AROWS; r++) {
                float p = sp[r * NSEQ + jg];
                acc[r].x += p * v4.x;
                acc[r].y += p * v4.y;
                acc[r].z += p * v4.z;
                acc[r].w += p * v4.w;
            }
        }
    }

    // reduce js halves within warp (lane l += lane l+16)
#pragma unroll
    for (int r = 0; r < AROWS; r++) {
        acc[r].x += __shfl_down_sync(0xffffffffu, acc[r].x, 16);
        acc[r].y += __shfl_down_sync(0xffffffffu, acc[r].y, 16);
        acc[r].z += __shfl_down_sync(0xffffffffu, acc[r].z, 16);
        acc[r].w += __shfl_down_sync(0xffffffffu, acc[r].w, 16);
    }

    __syncthreads();              // everyone done reading sp -> reuse as reduce buffer
    if (lane < 16) {
#pragma unroll
        for (int r = 0; r < AROWS; r++)
            sp4[w * 256 + r * 16 + d4] = acc[r];
    }
    __syncthreads();

    // final cross-warp reduction: 256 float4 outputs
    if (tid < 256) {
        float4 o4 = make_float4(0.f, 0.f, 0.f, 0.f);
#pragma unroll
        for (int ww = 0; ww < 16; ww++) {
            float4 t4 = sp4[ww * 256 + tid];
            o4.x += t4.x; o4.y += t4.y; o4.z += t4.z; o4.w += t4.w;
        }
        int r   = tid >> 4;
        int dd4 = tid & 15;
        float4* dst = (float4*)(g_attn + (size_t)(b * NSEQ + n0 + r) * DIM + h * HD);
        dst[dd4] = o4;
    }
}

// ---------------------------------------------------------------------------
extern "C" void kernel_launch(void* const* d_in, const int* in_sizes, int n_in,
                              void* d_out, int out_size)
{
    const float* x      = (const float*)d_in[0];
    const float* w_qkv  = (const float*)d_in[1];
    const float* w_proj = (const float*)d_in[2];
    const float* b_proj = (const float*)d_in[3];
    float* out = (float*)d_out;

    cudaFuncSetAttribute(attn_kernel,
                         cudaFuncAttributeMaxDynamicSharedMemorySize, SMEM_BYTES);

    // 1) QKV GEMM + scatter (q pre-scaled)
    sgemm_kernel<<<dim3(QKV_N / BN, MROWS / BM), 256>>>(
        x, w_qkv, nullptr, nullptr, MROWS, QKV_N, DIM, 0);

    // 2) fused attention (topk mask + softmax + PV)
    attn_kernel<<<dim3(NSEQ / AROWS, HEADS, Bb), 512, SMEM_BYTES>>>();

    // 3) output projection + bias
    sgemm_kernel<<<dim3(DIM / BN, MROWS / BM), 256>>>(
        nullptr, w_proj, out, b_proj, MROWS, DIM, DIM, 1);
}